// round 10
// baseline (speedup 1.0000x reference)
#include <cuda_runtime.h>
#include <cuda_bf16.h>
#include <cstdint>
#include <cstddef>

// LSTM: B=64, T=512, D=512, H=512, fp32.
// Phase 0: interleave U gates -> g_U4[k*512+h] = (Uc,Ui,Uf,Uo)[k][h]
// Phase 1: P[t][b][g*512+h] = x @ W_g + b_g  (SGEMM, f32x2 FFMA)
// Phase 2: ONE persistent kernel, 128 CTAs x 512 threads, U register-resident,
//          warp-uniform ks (conflict-free smem), per-batch-group barriers.

typedef unsigned long long ull;

#define B_ 64
#define T_ 512
#define D_ 512
#define H_ 512

// ---------------- device scratch (static: no allocation APIs) ----------------
__device__ float      g_P[(size_t)T_ * B_ * 2048];   // 256 MB preactivations
__device__ ulonglong2 g_U4[(size_t)D_ * H_];         // 4 MB gate-interleaved U
__device__ float      g_h2[2][(size_t)H_ * B_];      // ping-pong h, layout [h][b]
__device__ unsigned   g_cnt[4 * 32];                  // per-bg barrier counters

// ---------------- f32x2 helpers ----------------
__device__ __forceinline__ void ffma2(ull& d, ull a, ull b) {
    asm("fma.rn.f32x2 %0, %1, %2, %0;" : "+l"(d) : "l"(a), "l"(b));
}
__device__ __forceinline__ ull pack2(float v) {
    ull r; asm("mov.b64 %0, {%1, %1};" : "=l"(r) : "f"(v)); return r;
}
__device__ __forceinline__ float2 up2(ull v) {
    float2 r; asm("mov.b64 {%0, %1}, %2;" : "=f"(r.x), "=f"(r.y) : "l"(v)); return r;
}
__device__ __forceinline__ unsigned ldv(const unsigned* p) {
    unsigned v; asm volatile("ld.volatile.global.u32 %0, [%1];" : "=r"(v) : "l"(p)); return v;
}

// ---------------- phase 0: build interleaved U + reset state ----------------
__global__ void build_u4(const float* __restrict__ Uc, const float* __restrict__ Ui,
                         const float* __restrict__ Uf, const float* __restrict__ Uo) {
    int i = blockIdx.x * 256 + threadIdx.x;   // i = k*512 + h
    float4 v = make_float4(Uc[i], Ui[i], Uf[i], Uo[i]);
    ((float4*)g_U4)[i] = v;
}

__global__ void zero_init() {
    int i = blockIdx.x * 256 + threadIdx.x;   // 128*256 = 32768 = H_*B_
    g_h2[0][i] = 0.f;
    if (i < 4 * 32) g_cnt[i] = 0u;
}

// ---------------- phase 1: SGEMM for preactivations ----------------
#define BM 128
#define BN 128
#define BK 8

__global__ void gemm_pre(const float* __restrict__ A,
                         const float* __restrict__ Wc, const float* __restrict__ Wi,
                         const float* __restrict__ Wf, const float* __restrict__ Wo,
                         const float* __restrict__ bc, const float* __restrict__ bi,
                         const float* __restrict__ bf, const float* __restrict__ bo) {
    __shared__ __align__(16) float As[BK][BM];
    __shared__ __align__(16) float Bs[BK][BN];

    const int tid   = threadIdx.x;
    const int ntile = blockIdx.x;              // 0..15
    const int m0    = blockIdx.y * BM;
    const int gate  = ntile >> 2;
    const int hbase = (ntile & 3) * BN;
    const float* W    = (gate == 0) ? Wc : (gate == 1) ? Wi : (gate == 2) ? Wf : Wo;
    const float* bias = (gate == 0) ? bc : (gate == 1) ? bi : (gate == 2) ? bf : bo;

    const int a_row = tid >> 1, a_col = (tid & 1) * 4;
    const int b_row = tid >> 5, b_col = (tid & 31) * 4;
    const int tx = tid & 15, ty = tid >> 4;

    ull acc[4][8];
#pragma unroll
    for (int i = 0; i < 4; i++)
#pragma unroll
        for (int j = 0; j < 8; j++) acc[i][j] = 0ull;

    const float* Abase = A + (size_t)(m0 + a_row) * D_ + a_col;
    const float* Wbase = W + (size_t)b_row * H_ + hbase + b_col;

    for (int k0 = 0; k0 < D_; k0 += BK) {
        float4 av = *(const float4*)(Abase + k0);
        As[a_col + 0][a_row] = av.x;
        As[a_col + 1][a_row] = av.y;
        As[a_col + 2][a_row] = av.z;
        As[a_col + 3][a_row] = av.w;
        *(float4*)&Bs[b_row][b_col] = *(const float4*)(Wbase + (size_t)k0 * H_);
        __syncthreads();

#pragma unroll
        for (int kk = 0; kk < BK; kk++) {
            const ull* a64 = (const ull*)&As[kk][0];
            ull aP[4];
            aP[0] = a64[ty * 2];
            aP[1] = a64[ty * 2 + 1];
            aP[2] = a64[ty * 2 + 32];
            aP[3] = a64[ty * 2 + 33];
            float4 bv0 = *(const float4*)&Bs[kk][tx * 4];
            float4 bv1 = *(const float4*)&Bs[kk][tx * 4 + 64];
            ull bp[8];
            bp[0] = pack2(bv0.x); bp[1] = pack2(bv0.y);
            bp[2] = pack2(bv0.z); bp[3] = pack2(bv0.w);
            bp[4] = pack2(bv1.x); bp[5] = pack2(bv1.y);
            bp[6] = pack2(bv1.z); bp[7] = pack2(bv1.w);
#pragma unroll
            for (int ip = 0; ip < 4; ip++)
#pragma unroll
                for (int j = 0; j < 8; j++) ffma2(acc[ip][j], aP[ip], bp[j]);
        }
        __syncthreads();
    }

    float bias0[4], bias1[4];
#pragma unroll
    for (int j = 0; j < 4; j++) {
        bias0[j] = __ldg(&bias[hbase + tx * 4 + j]);
        bias1[j] = __ldg(&bias[hbase + 64 + tx * 4 + j]);
    }
#pragma unroll
    for (int ip = 0; ip < 4; ip++) {
        const int m_l = (ip < 2) ? (ty * 4 + ip * 2) : (64 + ty * 4 + (ip - 2) * 2);
        float2 c0 = up2(acc[ip][0]), c1 = up2(acc[ip][1]);
        float2 c2 = up2(acc[ip][2]), c3 = up2(acc[ip][3]);
        float2 c4 = up2(acc[ip][4]), c5 = up2(acc[ip][5]);
        float2 c6 = up2(acc[ip][6]), c7 = up2(acc[ip][7]);
#pragma unroll
        for (int lane = 0; lane < 2; lane++) {
            const int row = m0 + m_l + lane;        // row = b*512 + t
            const int b = row >> 9, t = row & 511;
            float* dst = g_P + ((size_t)(t * B_ + b)) * 2048 + (size_t)gate * 512 + hbase;
            float4 v0, v1;
            if (lane == 0) {
                v0 = make_float4(c0.x + bias0[0], c1.x + bias0[1], c2.x + bias0[2], c3.x + bias0[3]);
                v1 = make_float4(c4.x + bias1[0], c5.x + bias1[1], c6.x + bias1[2], c7.x + bias1[3]);
            } else {
                v0 = make_float4(c0.y + bias0[0], c1.y + bias0[1], c2.y + bias0[2], c3.y + bias0[3]);
                v1 = make_float4(c4.y + bias1[0], c5.y + bias1[1], c6.y + bias1[2], c7.y + bias1[3]);
            }
            *(float4*)(dst + tx * 4)      = v0;
            *(float4*)(dst + 64 + tx * 4) = v1;
        }
    }
}

// ---------------- phase 2: persistent recurrence ----------------
// 128 CTAs = 4 bg x 32 hg. CTA tile: 16 b x 16 h. 512 threads (16 warps).
// Thread: h_l = tid&15, bh = (tid>>4)&1 (b-half), ks = tid>>5 (32-k slice).
// A warp has UNIFORM ks -> inner-loop LDS is a 2-address broadcast, 64B apart:
// conflict-free, 1 wavefront. U slice = 64 ull regs. acc in 2 passes of 4 b.

#define SH_STRIDE 36                       // floats per sHd row (32 data + 4 pad)
#define SHD_BYTES  (D_ * SH_STRIDE * 4)    // 73728 B
#define SRED_ULLS  (16 * 16 * 34)          // [ks16][h16][16b*2 + 2 pad]
#define SMEM_REC   (SHD_BYTES + SRED_ULLS * 8)

__global__ void __launch_bounds__(512, 1) lstm_rec(float* __restrict__ out) {
    extern __shared__ __align__(16) char smem[];
    float* sHd  = (float*)smem;                     // [512][36] duplicated h pairs
    ull*   sRed = (ull*)(smem + SHD_BYTES);         // [16][16][34]

    const int tid = threadIdx.x;
    const int hg = blockIdx.x & 31, bg = blockIdx.x >> 5;
    const int h0 = hg * 16, b0 = bg * 16;
    const int h_l = tid & 15;
    const int bh  = (tid >> 4) & 1;
    const int ks  = tid >> 5;                        // 0..15, warp-uniform
    const int kbase = ks * 32;
    const int eb = tid >> 4;                         // epilogue b (valid tid<256)
    unsigned* bar = &g_cnt[bg * 32];

    // prologue: U slice (32 k x 4 gates) into 64 registers
    ull uA[32], uB[32];
#pragma unroll
    for (int i = 0; i < 32; i++) {
        ulonglong2 v = g_U4[(size_t)(kbase + i) * H_ + h0 + h_l];
        uA[i] = v.x;                                 // (Uc, Ui)
        uB[i] = v.y;                                 // (Uf, Uo)
    }

    float c_reg = 0.f;
    const float* Pbase = g_P + (size_t)(b0 + (eb & 15)) * 2048 + h0 + h_l;

    for (int t = 0; t < T_; t++) {
        // stage h_{t-1}: global [h][b] -> smem duplicated pairs {h,h}
        {
            const float* hb = g_h2[t & 1];
            float4 v[4];
#pragma unroll
            for (int j = 0; j < 4; j++) {
                int task = tid + j * 512;
                int k = task >> 2, q = task & 3;
                v[j] = *(const float4*)(hb + (size_t)k * B_ + b0 + q * 4);
            }
#pragma unroll
            for (int j = 0; j < 4; j++) {
                int task = tid + j * 512;
                int k = task >> 2, q = task & 3;
                *(float4*)&sHd[k * SH_STRIDE + q * 8] =
                    make_float4(v[j].x, v[j].x, v[j].y, v[j].y);
                *(float4*)&sHd[k * SH_STRIDE + q * 8 + 4] =
                    make_float4(v[j].z, v[j].z, v[j].w, v[j].w);
            }
        }

        // prefetch this step's input preactivations (epilogue threads only)
        float p0 = 0.f, p1 = 0.f, p2 = 0.f, p3 = 0.f;
        if (tid < 256) {
            const float* Pt = Pbase + (size_t)t * B_ * 2048;
            p0 = __ldg(Pt);
            p1 = __ldg(Pt + 512);
            p2 = __ldg(Pt + 1024);
            p3 = __ldg(Pt + 1536);
        }
        __syncthreads();

        // partial gate sums over this thread's 32-k slice, 8 b's in 2 passes
        ull* rb = sRed + (ks * 16 + h_l) * 34 + bh * 16;
#pragma unroll
        for (int pass = 0; pass < 2; pass++) {
            ull acc[4][2];
#pragma unroll
            for (int j = 0; j < 4; j++) { acc[j][0] = 0ull; acc[j][1] = 0ull; }

#pragma unroll
            for (int i = 0; i < 32; i++) {
                const ulonglong2* row =
                    (const ulonglong2*)&sHd[(kbase + i) * SH_STRIDE] + bh * 4 + pass * 2;
                ull ua = uA[i], ub = uB[i];
                ulonglong2 hp0 = row[0];
                ulonglong2 hp1 = row[1];
                ffma2(acc[0][0], hp0.x, ua); ffma2(acc[0][1], hp0.x, ub);
                ffma2(acc[1][0], hp0.y, ua); ffma2(acc[1][1], hp0.y, ub);
                ffma2(acc[2][0], hp1.x, ua); ffma2(acc[2][1], hp1.x, ub);
                ffma2(acc[3][0], hp1.y, ua); ffma2(acc[3][1], hp1.y, ub);
            }
#pragma unroll
            for (int j = 0; j < 4; j++) {
                rb[(pass * 4 + j) * 2]     = acc[j][0];
                rb[(pass * 4 + j) * 2 + 1] = acc[j][1];
            }
        }
        __syncthreads();

        // epilogue: 256 threads own (b = eb, h = h_l)
        if (tid < 256) {
            float pc = p0, pi = p1, pf = p2, po = p3;
#pragma unroll
            for (int kk = 0; kk < 16; kk++) {
                ulonglong2 rr = *(const ulonglong2*)(sRed + (kk * 16 + h_l) * 34 + eb * 2);
                float2 v0 = up2(rr.x);
                float2 v1 = up2(rr.y);
                pc += v0.x; pi += v0.y; pf += v1.x; po += v1.y;
            }
            float a  = tanhf(pc);
            float ig = 1.f / (1.f + __expf(-pi));
            float fg = 1.f / (1.f + __expf(-pf));
            float og = 1.f / (1.f + __expf(-po));
            c_reg = ig * a + fg * c_reg;
            float hn = og * tanhf(c_reg);

            out[((size_t)(b0 + eb) * T_ + t) * H_ + h0 + h_l] = hn;
            g_h2[(t + 1) & 1][(size_t)(h0 + h_l) * B_ + b0 + eb] = hn;
        }

        // inter-CTA barrier, scoped to this batch-group (32 CTAs)
        if (t < T_ - 1) {
            __threadfence();
            __syncthreads();
            if (tid == 0) {
                atomicAdd(bar, 1u);
                unsigned target = 32u * (unsigned)(t + 1);
                while (ldv(bar) < target) {}
                __threadfence();
            }
            __syncthreads();
        }
    }
}

// ---------------- launch ----------------
extern "C" void kernel_launch(void* const* d_in, const int* in_sizes, int n_in,
                              void* d_out, int out_size) {
    const float* x  = (const float*)d_in[0];
    const float* Wc = (const float*)d_in[1];
    const float* Wi = (const float*)d_in[2];
    const float* Wf = (const float*)d_in[3];
    const float* Wo = (const float*)d_in[4];
    const float* Uc = (const float*)d_in[5];
    const float* Ui = (const float*)d_in[6];
    const float* Uf = (const float*)d_in[7];
    const float* Uo = (const float*)d_in[8];
    const float* bc = (const float*)d_in[9];
    const float* bi = (const float*)d_in[10];
    const float* bf = (const float*)d_in[11];
    const float* bo = (const float*)d_in[12];
    float* out = (float*)d_out;

    static bool attr_set = false;
    if (!attr_set) {
        cudaFuncSetAttribute(lstm_rec, cudaFuncAttributeMaxDynamicSharedMemorySize, SMEM_REC);
        attr_set = true;
    }

    zero_init<<<128, 256>>>();
    build_u4<<<(D_ * H_) / 256, 256>>>(Uc, Ui, Uf, Uo);

    dim3 ggrid(2048 / BN, (B_ * T_) / BM);   // (16, 256)
    gemm_pre<<<ggrid, 256>>>(x, Wc, Wi, Wf, Wo, bc, bi, bf, bo);

    lstm_rec<<<128, 512, SMEM_REC>>>(out);
}

// round 11
// speedup vs baseline: 1.0959x; 1.0959x over previous
#include <cuda_runtime.h>
#include <cuda_bf16.h>
#include <cstdint>
#include <cstddef>

// LSTM: B=64, T=512, D=512, H=512, fp32.
// Phase 0: interleave U gates -> g_U4[k*512+h] = (Uc,Ui,Uf,Uo)[k][h]
// Phase 1: P[t][b][g*512+h] = x @ W_g + b_g  (SGEMM, f32x2 FFMA)
// Phase 2: ONE persistent kernel, 128 CTAs x 512 threads.
//          U tile lives in SHARED MEMORY (128 KB/CTA) -> regs ~50, no spills.
//          Thread = (h_l 16, bq 4, ks 8): 4 b x 64 k, acc in 8 ull regs.

typedef unsigned long long ull;

#define B_ 64
#define T_ 512
#define D_ 512
#define H_ 512

// ---------------- device scratch (static: no allocation APIs) ----------------
__device__ float      g_P[(size_t)T_ * B_ * 2048];   // 256 MB preactivations
__device__ ulonglong2 g_U4[(size_t)D_ * H_];         // 4 MB gate-interleaved U
__device__ float      g_h2[2][(size_t)H_ * B_];      // ping-pong h, layout [h][b]
__device__ unsigned   g_cnt[4 * 32];                  // per-bg barrier counters

// ---------------- f32x2 helpers ----------------
__device__ __forceinline__ void ffma2(ull& d, ull a, ull b) {
    asm("fma.rn.f32x2 %0, %1, %2, %0;" : "+l"(d) : "l"(a), "l"(b));
}
__device__ __forceinline__ ull pack2(float v) {
    ull r; asm("mov.b64 %0, {%1, %1};" : "=l"(r) : "f"(v)); return r;
}
__device__ __forceinline__ float2 up2(ull v) {
    float2 r; asm("mov.b64 {%0, %1}, %2;" : "=f"(r.x), "=f"(r.y) : "l"(v)); return r;
}
__device__ __forceinline__ unsigned ldv(const unsigned* p) {
    unsigned v; asm volatile("ld.volatile.global.u32 %0, [%1];" : "=r"(v) : "l"(p)); return v;
}

// ---------------- phase 0: build interleaved U + reset state ----------------
__global__ void build_u4(const float* __restrict__ Uc, const float* __restrict__ Ui,
                         const float* __restrict__ Uf, const float* __restrict__ Uo) {
    int i = blockIdx.x * 256 + threadIdx.x;   // i = k*512 + h
    float4 v = make_float4(Uc[i], Ui[i], Uf[i], Uo[i]);
    ((float4*)g_U4)[i] = v;
}

__global__ void zero_init() {
    int i = blockIdx.x * 256 + threadIdx.x;   // 128*256 = 32768 = H_*B_
    g_h2[0][i] = 0.f;
    if (i < 4 * 32) g_cnt[i] = 0u;
}

// ---------------- phase 1: SGEMM for preactivations ----------------
#define BM 128
#define BN 128
#define BK 8

__global__ void gemm_pre(const float* __restrict__ A,
                         const float* __restrict__ Wc, const float* __restrict__ Wi,
                         const float* __restrict__ Wf, const float* __restrict__ Wo,
                         const float* __restrict__ bc, const float* __restrict__ bi,
                         const float* __restrict__ bf, const float* __restrict__ bo) {
    __shared__ __align__(16) float As[BK][BM];
    __shared__ __align__(16) float Bs[BK][BN];

    const int tid   = threadIdx.x;
    const int ntile = blockIdx.x;              // 0..15
    const int m0    = blockIdx.y * BM;
    const int gate  = ntile >> 2;
    const int hbase = (ntile & 3) * BN;
    const float* W    = (gate == 0) ? Wc : (gate == 1) ? Wi : (gate == 2) ? Wf : Wo;
    const float* bias = (gate == 0) ? bc : (gate == 1) ? bi : (gate == 2) ? bf : bo;

    const int a_row = tid >> 1, a_col = (tid & 1) * 4;
    const int b_row = tid >> 5, b_col = (tid & 31) * 4;
    const int tx = tid & 15, ty = tid >> 4;

    ull acc[4][8];
#pragma unroll
    for (int i = 0; i < 4; i++)
#pragma unroll
        for (int j = 0; j < 8; j++) acc[i][j] = 0ull;

    const float* Abase = A + (size_t)(m0 + a_row) * D_ + a_col;
    const float* Wbase = W + (size_t)b_row * H_ + hbase + b_col;

    for (int k0 = 0; k0 < D_; k0 += BK) {
        float4 av = *(const float4*)(Abase + k0);
        As[a_col + 0][a_row] = av.x;
        As[a_col + 1][a_row] = av.y;
        As[a_col + 2][a_row] = av.z;
        As[a_col + 3][a_row] = av.w;
        *(float4*)&Bs[b_row][b_col] = *(const float4*)(Wbase + (size_t)k0 * H_);
        __syncthreads();

#pragma unroll
        for (int kk = 0; kk < BK; kk++) {
            const ull* a64 = (const ull*)&As[kk][0];
            ull aP[4];
            aP[0] = a64[ty * 2];
            aP[1] = a64[ty * 2 + 1];
            aP[2] = a64[ty * 2 + 32];
            aP[3] = a64[ty * 2 + 33];
            float4 bv0 = *(const float4*)&Bs[kk][tx * 4];
            float4 bv1 = *(const float4*)&Bs[kk][tx * 4 + 64];
            ull bp[8];
            bp[0] = pack2(bv0.x); bp[1] = pack2(bv0.y);
            bp[2] = pack2(bv0.z); bp[3] = pack2(bv0.w);
            bp[4] = pack2(bv1.x); bp[5] = pack2(bv1.y);
            bp[6] = pack2(bv1.z); bp[7] = pack2(bv1.w);
#pragma unroll
            for (int ip = 0; ip < 4; ip++)
#pragma unroll
                for (int j = 0; j < 8; j++) ffma2(acc[ip][j], aP[ip], bp[j]);
        }
        __syncthreads();
    }

    float bias0[4], bias1[4];
#pragma unroll
    for (int j = 0; j < 4; j++) {
        bias0[j] = __ldg(&bias[hbase + tx * 4 + j]);
        bias1[j] = __ldg(&bias[hbase + 64 + tx * 4 + j]);
    }
#pragma unroll
    for (int ip = 0; ip < 4; ip++) {
        const int m_l = (ip < 2) ? (ty * 4 + ip * 2) : (64 + ty * 4 + (ip - 2) * 2);
        float2 c0 = up2(acc[ip][0]), c1 = up2(acc[ip][1]);
        float2 c2 = up2(acc[ip][2]), c3 = up2(acc[ip][3]);
        float2 c4 = up2(acc[ip][4]), c5 = up2(acc[ip][5]);
        float2 c6 = up2(acc[ip][6]), c7 = up2(acc[ip][7]);
#pragma unroll
        for (int lane = 0; lane < 2; lane++) {
            const int row = m0 + m_l + lane;        // row = b*512 + t
            const int b = row >> 9, t = row & 511;
            float* dst = g_P + ((size_t)(t * B_ + b)) * 2048 + (size_t)gate * 512 + hbase;
            float4 v0, v1;
            if (lane == 0) {
                v0 = make_float4(c0.x + bias0[0], c1.x + bias0[1], c2.x + bias0[2], c3.x + bias0[3]);
                v1 = make_float4(c4.x + bias1[0], c5.x + bias1[1], c6.x + bias1[2], c7.x + bias1[3]);
            } else {
                v0 = make_float4(c0.y + bias0[0], c1.y + bias0[1], c2.y + bias0[2], c3.y + bias0[3]);
                v1 = make_float4(c4.y + bias1[0], c5.y + bias1[1], c6.y + bias1[2], c7.y + bias1[3]);
            }
            *(float4*)(dst + tx * 4)      = v0;
            *(float4*)(dst + 64 + tx * 4) = v1;
        }
    }
}

// ---------------- phase 2: persistent recurrence ----------------
// 128 CTAs = 4 bg x 32 hg. CTA tile: 16 b x 16 h. 512 threads (16 warps).
// Thread: h_l = tid&15, bq = (tid>>4)&3, ks = tid>>6 (64-k slice).
// Warp = 16 h_l x 2 bq, uniform ks -> all inner LDS conflict-free/broadcast.
// smem: sU [512k][16h] ulonglong2 (128 KB, staged once)
//       sHd [512k][16b dup-pairs]  (64 KB, unpadded: loads are k-uniform)
//       sRed [8ks][16h][34]        (34 KB)

#define SU_BYTES   (D_ * 16 * 16)              // 131072
#define SHD_BYTES  (D_ * 32 * 4)               // 65536
#define SRED_ULLS  (8 * 16 * 34)               // 4352
#define SMEM_REC   (SU_BYTES + SHD_BYTES + SRED_ULLS * 8)   // 231424

__global__ void __launch_bounds__(512, 1) lstm_rec(float* __restrict__ out) {
    extern __shared__ __align__(16) char smem[];
    ulonglong2* sU  = (ulonglong2*)smem;                    // [k*16 + h_l]
    float*      sHd = (float*)(smem + SU_BYTES);            // [k*32] dup pairs
    ull*        sRed = (ull*)(smem + SU_BYTES + SHD_BYTES); // [ks*16+h][34]

    const int tid = threadIdx.x;
    const int hg = blockIdx.x & 31, bg = blockIdx.x >> 5;
    const int h0 = hg * 16, b0 = bg * 16;
    const int h_l = tid & 15;
    const int bq  = (tid >> 4) & 3;
    const int ks  = tid >> 6;                   // 0..7, warp-uniform
    const int kbase = ks * 64;
    const int eb = tid >> 4;                    // epilogue b (valid tid<256)
    unsigned* bar = &g_cnt[bg * 32];

    // stage U tile into smem once: 8192 ulonglong2, 16 per thread (coalesced)
#pragma unroll
    for (int j = 0; j < 16; j++) {
        int idx = tid + j * 512;                // idx = k*16 + hh
        int k = idx >> 4, hh = idx & 15;
        sU[idx] = g_U4[(size_t)k * H_ + h0 + hh];
    }

    float c_reg = 0.f;
    const float* Pbase = g_P + (size_t)(b0 + (eb & 15)) * 2048 + h0 + h_l;

    __syncthreads();

    for (int t = 0; t < T_; t++) {
        // stage h_{t-1}: global [h][b] -> smem duplicated pairs {h,h}
        {
            const float* hb = g_h2[t & 1];
            float4 v[4];
#pragma unroll
            for (int j = 0; j < 4; j++) {
                int task = tid + j * 512;
                int k = task >> 2, q = task & 3;
                v[j] = *(const float4*)(hb + (size_t)k * B_ + b0 + q * 4);
            }
#pragma unroll
            for (int j = 0; j < 4; j++) {
                int task = tid + j * 512;
                int k = task >> 2, q = task & 3;
                *(float4*)&sHd[k * 32 + q * 8] =
                    make_float4(v[j].x, v[j].x, v[j].y, v[j].y);
                *(float4*)&sHd[k * 32 + q * 8 + 4] =
                    make_float4(v[j].z, v[j].z, v[j].w, v[j].w);
            }
        }

        // prefetch this step's input preactivations (epilogue threads only)
        float p0 = 0.f, p1 = 0.f, p2 = 0.f, p3 = 0.f;
        if (tid < 256) {
            const float* Pt = Pbase + (size_t)t * B_ * 2048;
            p0 = __ldg(Pt);
            p1 = __ldg(Pt + 512);
            p2 = __ldg(Pt + 1024);
            p3 = __ldg(Pt + 1536);
        }
        __syncthreads();

        // partial gate sums: 4 b x 64 k, U streamed from smem
        ull a00 = 0, a01 = 0, a10 = 0, a11 = 0;
        ull a20 = 0, a21 = 0, a30 = 0, a31 = 0;
        {
            const ulonglong2* Up = sU + kbase * 16 + h_l;
            const ulonglong2* Hp = (const ulonglong2*)&sHd[kbase * 32] + bq * 2;
#pragma unroll 8
            for (int i = 0; i < 64; i++) {
                ulonglong2 u   = Up[i * 16];        // (Uc,Ui | Uf,Uo)
                ulonglong2 hp0 = Hp[i * 8];         // {h dup, h' dup}
                ulonglong2 hp1 = Hp[i * 8 + 1];
                ffma2(a00, hp0.x, u.x); ffma2(a01, hp0.x, u.y);
                ffma2(a10, hp0.y, u.x); ffma2(a11, hp0.y, u.y);
                ffma2(a20, hp1.x, u.x); ffma2(a21, hp1.x, u.y);
                ffma2(a30, hp1.y, u.x); ffma2(a31, hp1.y, u.y);
            }
        }
        {
            ull* rb = sRed + (ks * 16 + h_l) * 34 + bq * 8;
            rb[0] = a00; rb[1] = a01;
            rb[2] = a10; rb[3] = a11;
            rb[4] = a20; rb[5] = a21;
            rb[6] = a30; rb[7] = a31;
        }
        __syncthreads();

        // epilogue: 256 threads own (b = eb, h = h_l)
        if (tid < 256) {
            float pc = p0, pi = p1, pf = p2, po = p3;
#pragma unroll
            for (int kk = 0; kk < 8; kk++) {
                ulonglong2 rr = *(const ulonglong2*)(sRed + (kk * 16 + h_l) * 34 + eb * 2);
                float2 v0 = up2(rr.x);
                float2 v1 = up2(rr.y);
                pc += v0.x; pi += v0.y; pf += v1.x; po += v1.y;
            }
            float a  = tanhf(pc);
            float ig = 1.f / (1.f + __expf(-pi));
            float fg = 1.f / (1.f + __expf(-pf));
            float og = 1.f / (1.f + __expf(-po));
            c_reg = ig * a + fg * c_reg;
            float hn = og * tanhf(c_reg);

            out[((size_t)(b0 + eb) * T_ + t) * H_ + h0 + h_l] = hn;
            g_h2[(t + 1) & 1][(size_t)(h0 + h_l) * B_ + b0 + eb] = hn;
        }

        // inter-CTA barrier, scoped to this batch-group (32 CTAs)
        if (t < T_ - 1) {
            __threadfence();
            __syncthreads();
            if (tid == 0) {
                atomicAdd(bar, 1u);
                unsigned target = 32u * (unsigned)(t + 1);
                while (ldv(bar) < target) {}
                __threadfence();
            }
            __syncthreads();
        }
    }
}

// ---------------- launch ----------------
extern "C" void kernel_launch(void* const* d_in, const int* in_sizes, int n_in,
                              void* d_out, int out_size) {
    const float* x  = (const float*)d_in[0];
    const float* Wc = (const float*)d_in[1];
    const float* Wi = (const float*)d_in[2];
    const float* Wf = (const float*)d_in[3];
    const float* Wo = (const float*)d_in[4];
    const float* Uc = (const float*)d_in[5];
    const float* Ui = (const float*)d_in[6];
    const float* Uf = (const float*)d_in[7];
    const float* Uo = (const float*)d_in[8];
    const float* bc = (const float*)d_in[9];
    const float* bi = (const float*)d_in[10];
    const float* bf = (const float*)d_in[11];
    const float* bo = (const float*)d_in[12];
    float* out = (float*)d_out;

    static bool attr_set = false;
    if (!attr_set) {
        cudaFuncSetAttribute(lstm_rec, cudaFuncAttributeMaxDynamicSharedMemorySize, SMEM_REC);
        attr_set = true;
    }

    zero_init<<<128, 256>>>();
    build_u4<<<(D_ * H_) / 256, 256>>>(Uc, Ui, Uf, Uo);

    dim3 ggrid(2048 / BN, (B_ * T_) / BM);   // (16, 256)
    gemm_pre<<<ggrid, 256>>>(x, Wc, Wi, Wf, Wo, bc, bi, bf, bo);

    lstm_rec<<<128, 512, SMEM_REC>>>(out);
}

// round 12
// speedup vs baseline: 1.1344x; 1.0352x over previous
#include <cuda_runtime.h>
#include <cuda_bf16.h>
#include <cstdint>
#include <cstddef>

// LSTM: B=64, T=512, D=512, H=512, fp32.
// Phase 0: interleave U gates -> g_U4[k*512+h] = (Uc,Ui,Uf,Uo)[k][h]
// Phase 1: P[t][b][g*512+h] = x @ W_g + b_g  (SGEMM, f32x2 FFMA)
// Phase 2: ONE persistent kernel, 128 CTAs x 512 threads.
//          U tile in smem (128 KB). Thread = (h_l 16, bh 2, ks 16):
//          8 b x 32 k per thread -> 16 FFMA2 per 5 LDS.128 (FMA-bound).
//          sRed aliases sHd (196 KB total, 1 CTA/SM guaranteed).

typedef unsigned long long ull;

#define B_ 64
#define T_ 512
#define D_ 512
#define H_ 512

// ---------------- device scratch (static: no allocation APIs) ----------------
__device__ float      g_P[(size_t)T_ * B_ * 2048];   // 256 MB preactivations
__device__ ulonglong2 g_U4[(size_t)D_ * H_];         // 4 MB gate-interleaved U
__device__ float      g_h2[2][(size_t)H_ * B_];      // ping-pong h, layout [h][b]
__device__ unsigned   g_cnt[4 * 32];                  // per-bg barrier counters

// ---------------- f32x2 helpers ----------------
__device__ __forceinline__ void ffma2(ull& d, ull a, ull b) {
    asm("fma.rn.f32x2 %0, %1, %2, %0;" : "+l"(d) : "l"(a), "l"(b));
}
__device__ __forceinline__ ull pack2(float v) {
    ull r; asm("mov.b64 %0, {%1, %1};" : "=l"(r) : "f"(v)); return r;
}
__device__ __forceinline__ float2 up2(ull v) {
    float2 r; asm("mov.b64 {%0, %1}, %2;" : "=f"(r.x), "=f"(r.y) : "l"(v)); return r;
}
__device__ __forceinline__ unsigned ldv(const unsigned* p) {
    unsigned v; asm volatile("ld.volatile.global.u32 %0, [%1];" : "=r"(v) : "l"(p)); return v;
}

// ---------------- phase 0: build interleaved U + reset state ----------------
__global__ void build_u4(const float* __restrict__ Uc, const float* __restrict__ Ui,
                         const float* __restrict__ Uf, const float* __restrict__ Uo) {
    int i = blockIdx.x * 256 + threadIdx.x;   // i = k*512 + h
    float4 v = make_float4(Uc[i], Ui[i], Uf[i], Uo[i]);
    ((float4*)g_U4)[i] = v;
}

__global__ void zero_init() {
    int i = blockIdx.x * 256 + threadIdx.x;   // 128*256 = 32768 = H_*B_
    g_h2[0][i] = 0.f;
    if (i < 4 * 32) g_cnt[i] = 0u;
}

// ---------------- phase 1: SGEMM for preactivations ----------------
#define BM 128
#define BN 128
#define BK 8

__global__ void gemm_pre(const float* __restrict__ A,
                         const float* __restrict__ Wc, const float* __restrict__ Wi,
                         const float* __restrict__ Wf, const float* __restrict__ Wo,
                         const float* __restrict__ bc, const float* __restrict__ bi,
                         const float* __restrict__ bf, const float* __restrict__ bo) {
    __shared__ __align__(16) float As[BK][BM];
    __shared__ __align__(16) float Bs[BK][BN];

    const int tid   = threadIdx.x;
    const int ntile = blockIdx.x;              // 0..15
    const int m0    = blockIdx.y * BM;
    const int gate  = ntile >> 2;
    const int hbase = (ntile & 3) * BN;
    const float* W    = (gate == 0) ? Wc : (gate == 1) ? Wi : (gate == 2) ? Wf : Wo;
    const float* bias = (gate == 0) ? bc : (gate == 1) ? bi : (gate == 2) ? bf : bo;

    const int a_row = tid >> 1, a_col = (tid & 1) * 4;
    const int b_row = tid >> 5, b_col = (tid & 31) * 4;
    const int tx = tid & 15, ty = tid >> 4;

    ull acc[4][8];
#pragma unroll
    for (int i = 0; i < 4; i++)
#pragma unroll
        for (int j = 0; j < 8; j++) acc[i][j] = 0ull;

    const float* Abase = A + (size_t)(m0 + a_row) * D_ + a_col;
    const float* Wbase = W + (size_t)b_row * H_ + hbase + b_col;

    for (int k0 = 0; k0 < D_; k0 += BK) {
        float4 av = *(const float4*)(Abase + k0);
        As[a_col + 0][a_row] = av.x;
        As[a_col + 1][a_row] = av.y;
        As[a_col + 2][a_row] = av.z;
        As[a_col + 3][a_row] = av.w;
        *(float4*)&Bs[b_row][b_col] = *(const float4*)(Wbase + (size_t)k0 * H_);
        __syncthreads();

#pragma unroll
        for (int kk = 0; kk < BK; kk++) {
            const ull* a64 = (const ull*)&As[kk][0];
            ull aP[4];
            aP[0] = a64[ty * 2];
            aP[1] = a64[ty * 2 + 1];
            aP[2] = a64[ty * 2 + 32];
            aP[3] = a64[ty * 2 + 33];
            float4 bv0 = *(const float4*)&Bs[kk][tx * 4];
            float4 bv1 = *(const float4*)&Bs[kk][tx * 4 + 64];
            ull bp[8];
            bp[0] = pack2(bv0.x); bp[1] = pack2(bv0.y);
            bp[2] = pack2(bv0.z); bp[3] = pack2(bv0.w);
            bp[4] = pack2(bv1.x); bp[5] = pack2(bv1.y);
            bp[6] = pack2(bv1.z); bp[7] = pack2(bv1.w);
#pragma unroll
            for (int ip = 0; ip < 4; ip++)
#pragma unroll
                for (int j = 0; j < 8; j++) ffma2(acc[ip][j], aP[ip], bp[j]);
        }
        __syncthreads();
    }

    float bias0[4], bias1[4];
#pragma unroll
    for (int j = 0; j < 4; j++) {
        bias0[j] = __ldg(&bias[hbase + tx * 4 + j]);
        bias1[j] = __ldg(&bias[hbase + 64 + tx * 4 + j]);
    }
#pragma unroll
    for (int ip = 0; ip < 4; ip++) {
        const int m_l = (ip < 2) ? (ty * 4 + ip * 2) : (64 + ty * 4 + (ip - 2) * 2);
        float2 c0 = up2(acc[ip][0]), c1 = up2(acc[ip][1]);
        float2 c2 = up2(acc[ip][2]), c3 = up2(acc[ip][3]);
        float2 c4 = up2(acc[ip][4]), c5 = up2(acc[ip][5]);
        float2 c6 = up2(acc[ip][6]), c7 = up2(acc[ip][7]);
#pragma unroll
        for (int lane = 0; lane < 2; lane++) {
            const int row = m0 + m_l + lane;        // row = b*512 + t
            const int b = row >> 9, t = row & 511;
            float* dst = g_P + ((size_t)(t * B_ + b)) * 2048 + (size_t)gate * 512 + hbase;
            float4 v0, v1;
            if (lane == 0) {
                v0 = make_float4(c0.x + bias0[0], c1.x + bias0[1], c2.x + bias0[2], c3.x + bias0[3]);
                v1 = make_float4(c4.x + bias1[0], c5.x + bias1[1], c6.x + bias1[2], c7.x + bias1[3]);
            } else {
                v0 = make_float4(c0.y + bias0[0], c1.y + bias0[1], c2.y + bias0[2], c3.y + bias0[3]);
                v1 = make_float4(c4.y + bias1[0], c5.y + bias1[1], c6.y + bias1[2], c7.y + bias1[3]);
            }
            *(float4*)(dst + tx * 4)      = v0;
            *(float4*)(dst + 64 + tx * 4) = v1;
        }
    }
}

// ---------------- phase 2: persistent recurrence ----------------
// 128 CTAs = 4 bg x 32 hg. CTA tile: 16 b x 16 h. 512 threads (16 warps).
// Thread: h_l = tid&15, bh = (tid>>4)&1 (8-b half), ks = tid>>5 (32-k slice).
// Warp = 16 h_l x 2 bh, uniform ks: U load 2 wf, h loads broadcast 1 wf each.
// Per k: 5 LDS.128 -> 16 FFMA2. Crossbar 3072 cyc/SM/step < FMA 4096.
// smem: sU [512k][16h] ulonglong2 (128 KB, staged once)
//       alias region (69632 B): sHd [512k][32] dup pairs (64 KB)
//                               sRed [16ks][16h][34] ull (68 KB)

#define SU_BYTES    (D_ * 16 * 16)             // 131072
#define ALIAS_BYTES (16 * 16 * 34 * 8)         // 69632 (>= SHD 65536)
#define SMEM_REC    (SU_BYTES + ALIAS_BYTES)   // 200704

__global__ void __launch_bounds__(512, 1) lstm_rec(float* __restrict__ out) {
    extern __shared__ __align__(16) char smem[];
    ulonglong2* sU   = (ulonglong2*)smem;                // [k*16 + h_l]
    float*      sHd  = (float*)(smem + SU_BYTES);        // [k*32] dup pairs
    ull*        sRed = (ull*)(smem + SU_BYTES);          // aliases sHd

    const int tid = threadIdx.x;
    const int hg = blockIdx.x & 31, bg = blockIdx.x >> 5;
    const int h0 = hg * 16, b0 = bg * 16;
    const int h_l = tid & 15;
    const int bh  = (tid >> 4) & 1;
    const int ks  = tid >> 5;                    // 0..15, warp-uniform
    const int kbase = ks * 32;
    const int eb = tid >> 4;                     // epilogue b (valid tid<256)
    unsigned* bar = &g_cnt[bg * 32];

    // stage U tile into smem once: 8192 ulonglong2, 16 per thread (coalesced)
#pragma unroll
    for (int j = 0; j < 16; j++) {
        int idx = tid + j * 512;                 // idx = k*16 + hh
        int k = idx >> 4, hh = idx & 15;
        sU[idx] = g_U4[(size_t)k * H_ + h0 + hh];
    }

    float c_reg = 0.f;
    const float* Pbase = g_P + (size_t)(b0 + (eb & 15)) * 2048 + h0 + h_l;

    __syncthreads();

    for (int t = 0; t < T_; t++) {
        // prefetch this step's input preactivations FIRST (deep MLP)
        float p0 = 0.f, p1 = 0.f, p2 = 0.f, p3 = 0.f;
        if (tid < 256) {
            const float* Pt = Pbase + (size_t)t * B_ * 2048;
            p0 = __ldg(Pt);
            p1 = __ldg(Pt + 512);
            p2 = __ldg(Pt + 1024);
            p3 = __ldg(Pt + 1536);
        }

        // stage h_{t-1}: global [h][b] -> smem duplicated pairs {h,h}
        {
            const float* hb = g_h2[t & 1];
            float4 v[4];
#pragma unroll
            for (int j = 0; j < 4; j++) {
                int task = tid + j * 512;
                int k = task >> 2, q = task & 3;
                v[j] = *(const float4*)(hb + (size_t)k * B_ + b0 + q * 4);
            }
#pragma unroll
            for (int j = 0; j < 4; j++) {
                int task = tid + j * 512;
                int k = task >> 2, q = task & 3;
                *(float4*)&sHd[k * 32 + q * 8] =
                    make_float4(v[j].x, v[j].x, v[j].y, v[j].y);
                *(float4*)&sHd[k * 32 + q * 8 + 4] =
                    make_float4(v[j].z, v[j].z, v[j].w, v[j].w);
            }
        }
        __syncthreads();

        // partial gate sums: 8 b x 32 k per thread, U streamed from smem
        ull acc[8][2];
#pragma unroll
        for (int j = 0; j < 8; j++) { acc[j][0] = 0ull; acc[j][1] = 0ull; }
        {
            const ulonglong2* Up = sU + kbase * 16 + h_l;
            const ulonglong2* Hp = (const ulonglong2*)sHd + kbase * 8 + bh * 4;
#pragma unroll 4
            for (int i = 0; i < 32; i++) {
                ulonglong2 u = Up[i * 16];          // (Uc,Ui | Uf,Uo)
                ulonglong2 hp0 = Hp[i * 8];         // {h0 dup, h1 dup}
                ulonglong2 hp1 = Hp[i * 8 + 1];
                ulonglong2 hp2 = Hp[i * 8 + 2];
                ulonglong2 hp3 = Hp[i * 8 + 3];
                ffma2(acc[0][0], hp0.x, u.x); ffma2(acc[0][1], hp0.x, u.y);
                ffma2(acc[1][0], hp0.y, u.x); ffma2(acc[1][1], hp0.y, u.y);
                ffma2(acc[2][0], hp1.x, u.x); ffma2(acc[2][1], hp1.x, u.y);
                ffma2(acc[3][0], hp1.y, u.x); ffma2(acc[3][1], hp1.y, u.y);
                ffma2(acc[4][0], hp2.x, u.x); ffma2(acc[4][1], hp2.x, u.y);
                ffma2(acc[5][0], hp2.y, u.x); ffma2(acc[5][1], hp2.y, u.y);
                ffma2(acc[6][0], hp3.x, u.x); ffma2(acc[6][1], hp3.x, u.y);
                ffma2(acc[7][0], hp3.y, u.x); ffma2(acc[7][1], hp3.y, u.y);
            }
        }
        __syncthreads();   // all reads of sHd done; safe to overwrite via sRed

        // dump partials (16 ull contiguous, 16B-aligned)
        {
            ulonglong2* rb = (ulonglong2*)(sRed + (ks * 16 + h_l) * 34 + bh * 16);
#pragma unroll
            for (int j = 0; j < 8; j++) {
                ulonglong2 v; v.x = acc[j][0]; v.y = acc[j][1];
                rb[j] = v;
            }
        }
        __syncthreads();

        // epilogue: 256 threads own (b = eb, h = h_l)
        if (tid < 256) {
            float pc = p0, pi = p1, pf = p2, po = p3;
#pragma unroll
            for (int kk = 0; kk < 16; kk++) {
                ulonglong2 rr = *(const ulonglong2*)(sRed + (kk * 16 + h_l) * 34 + eb * 2);
                float2 v0 = up2(rr.x);
                float2 v1 = up2(rr.y);
                pc += v0.x; pi += v0.y; pf += v1.x; po += v1.y;
            }
            float a  = tanhf(pc);
            float ig = 1.f / (1.f + __expf(-pi));
            float fg = 1.f / (1.f + __expf(-pf));
            float og = 1.f / (1.f + __expf(-po));
            c_reg = ig * a + fg * c_reg;
            float hn = og * tanhf(c_reg);

            out[((size_t)(b0 + eb) * T_ + t) * H_ + h0 + h_l] = hn;
            g_h2[(t + 1) & 1][(size_t)(h0 + h_l) * B_ + b0 + eb] = hn;
        }

        // inter-CTA barrier, scoped to this batch-group (32 CTAs)
        if (t < T_ - 1) {
            __threadfence();
            __syncthreads();
            if (tid == 0) {
                atomicAdd(bar, 1u);
                unsigned target = 32u * (unsigned)(t + 1);
                while (ldv(bar) < target) {}
                __threadfence();
            }
            __syncthreads();
        }
    }
}

// ---------------- launch ----------------
extern "C" void kernel_launch(void* const* d_in, const int* in_sizes, int n_in,
                              void* d_out, int out_size) {
    const float* x  = (const float*)d_in[0];
    const float* Wc = (const float*)d_in[1];
    const float* Wi = (const float*)d_in[2];
    const float* Wf = (const float*)d_in[3];
    const float* Wo = (const float*)d_in[4];
    const float* Uc = (const float*)d_in[5];
    const float* Ui = (const float*)d_in[6];
    const float* Uf = (const float*)d_in[7];
    const float* Uo = (const float*)d_in[8];
    const float* bc = (const float*)d_in[9];
    const float* bi = (const float*)d_in[10];
    const float* bf = (const float*)d_in[11];
    const float* bo = (const float*)d_in[12];
    float* out = (float*)d_out;

    static bool attr_set = false;
    if (!attr_set) {
        cudaFuncSetAttribute(lstm_rec, cudaFuncAttributeMaxDynamicSharedMemorySize, SMEM_REC);
        attr_set = true;
    }

    zero_init<<<128, 256>>>();
    build_u4<<<(D_ * H_) / 256, 256>>>(Uc, Ui, Uf, Uo);

    dim3 ggrid(2048 / BN, (B_ * T_) / BM);   // (16, 256)
    gemm_pre<<<ggrid, 256>>>(x, Wc, Wi, Wf, Wo, bc, bi, bf, bo);

    lstm_rec<<<128, 512, SMEM_REC>>>(out);
}